// round 11
// baseline (speedup 1.0000x reference)
#include <cuda_runtime.h>
#include <cuda_fp16.h>
#include <cstdint>

// CorrTorch via warp-level fp16 mma.sync (m16n8k16).
// R11: M=64 (full x-row) per warp at 192 thr / 2 blocks (170-reg cap), with
// R10's kc-merged pipeline (prefetch next-it kc0, JIT kc1). Full row => no
// edge loads at all; x=31/32 seam via cross-half shuffles (proven in R9).
// Weight LDS.128 amortized over 64 voxels (halves weight wavefronts/voxel).

#define C_    32
#define NOFF_ 27
#define VOX   262144                  // 64^3
#define PAIRS 16                      // channel pairs
#define NCHUNK 54                     // 27 offsets * 2 k16-chunks
#define WQ_ELEMS (NCHUNK * 64)        // uint4 count = 3456 (55296 B)
#define TPB   192
#define WPB   6

__device__ uint4 WQ_g[WQ_ELEMS];            // packed fp16 weight fragments
__device__ uint32_t IN1H[PAIRS * VOX];      // half2 per voxel (16 MB)
__device__ uint32_t IN2H[PAIRS * VOX];      // half2 per voxel (16 MB)

__device__ __forceinline__ uint32_t f2h2(float lo, float hi) {
    uint32_t r;
    asm("cvt.rn.f16x2.f32 %0, %1, %2;" : "=r"(r) : "f"(hi), "f"(lo));
    return r;
}
__device__ __forceinline__ uint32_t hmul2(uint32_t a, uint32_t b) {
    uint32_t d;
    asm("mul.rn.f16x2 %0, %1, %2;" : "=r"(d) : "r"(a), "r"(b));
    return d;
}

// ---------------- input conversion prepass ----------------
__global__ void convert_inputs(const float* __restrict__ in1,
                               const float* __restrict__ in2) {
    const int idx = blockIdx.x * 256 + threadIdx.x;
    const int per_arr = PAIRS * VOX / 4;           // 1M
    if (idx >= 2 * per_arr) return;
    const int arr = (idx >= per_arr);
    const int r = idx - arr * per_arr;
    const int c2 = r / (VOX / 4);
    const int v4 = (r - c2 * (VOX / 4)) * 4;
    const float* src = arr ? in2 : in1;
    uint32_t* dst = arr ? IN2H : IN1H;
    const float4 a = __ldg(reinterpret_cast<const float4*>(src + (2 * c2) * VOX + v4));
    const float4 b = __ldg(reinterpret_cast<const float4*>(src + (2 * c2 + 1) * VOX + v4));
    uint4 o;
    o.x = f2h2(a.x, b.x); o.y = f2h2(a.y, b.y);
    o.z = f2h2(a.z, b.z); o.w = f2h2(a.w, b.w);
    *reinterpret_cast<uint4*>(dst + c2 * VOX + v4) = o;
}

// ---------------- weight staging (layout as R6-R10) ----------------
__global__ void stage_weights(const float* __restrict__ w) {
    int idx = blockIdx.x * blockDim.x + threadIdx.x;
    if (idx >= WQ_ELEMS) return;
    int chunk = idx >> 6;            // off*2 + kc
    int rem = idx & 63;
    int h = rem >> 5;
    int lane = rem & 31;
    int off = chunk >> 1, kc = chunk & 1;
    int tg = lane >> 2, tk = lane & 3;
    int k0 = off * 32 + kc * 16;
    const float s = 0.17677669529663688f;   // 1/sqrt(32)
    int oa = (2 * h) * 8 + tg;
    int ob = (2 * h + 1) * 8 + tg;
    uint4 r;
    r.x = f2h2(w[oa * 864 + k0 + 2 * tk] * s,     w[oa * 864 + k0 + 2 * tk + 1] * s);
    r.y = f2h2(w[oa * 864 + k0 + 2 * tk + 8] * s, w[oa * 864 + k0 + 2 * tk + 9] * s);
    r.z = (ob < NOFF_) ? f2h2(w[ob * 864 + k0 + 2 * tk] * s,
                              w[ob * 864 + k0 + 2 * tk + 1] * s) : 0u;
    r.w = (ob < NOFF_) ? f2h2(w[ob * 864 + k0 + 2 * tk + 8] * s,
                              w[ob * 864 + k0 + 2 * tk + 9] * s) : 0u;
    WQ_g[idx] = r;
}

// ---------------- mma helper ----------------
__device__ __forceinline__ void mma16816(float* d, uint32_t a0, uint32_t a1,
                                         uint32_t a2, uint32_t a3,
                                         uint32_t b0, uint32_t b1) {
    asm volatile(
        "mma.sync.aligned.m16n8k16.row.col.f32.f16.f16.f32 "
        "{%0,%1,%2,%3}, {%4,%5,%6,%7}, {%8,%9}, {%0,%1,%2,%3};"
        : "+f"(d[0]), "+f"(d[1]), "+f"(d[2]), "+f"(d[3])
        : "r"(a0), "r"(a1), "r"(a2), "r"(a3), "r"(b0), "r"(b1));
}

// 8 mma for one half at one dx
__device__ __forceinline__ void half_mma(float* m0, float* m1,
                                         const uint32_t* i1a, const uint32_t* i1b,
                                         const uint32_t* wv0, const uint32_t* wv1,
                                         int dx, const uint4& wA, const uint4& wB) {
#pragma unroll
    for (int mt = 0; mt < 2; mt++) {
        const int p0 = 2 * mt, p1 = 2 * mt + 1;
        const uint32_t a0 = hmul2(i1a[p0], wv0[dx + p0]);
        const uint32_t a1 = hmul2(i1a[p1], wv0[dx + p1]);
        const uint32_t a2 = hmul2(i1b[p0], wv1[dx + p0]);
        const uint32_t a3 = hmul2(i1b[p1], wv1[dx + p1]);
        float* acc = mt ? m1 : m0;
        mma16816(acc + 0,  a0, a1, a2, a3, wA.x, wA.y);
        mma16816(acc + 4,  a0, a1, a2, a3, wA.z, wA.w);
        mma16816(acc + 8,  a0, a1, a2, a3, wB.x, wB.y);
        mma16816(acc + 12, a0, a1, a2, a3, wB.z, wB.w);
    }
}

// ---------------- main kernel ----------------
__global__ void __launch_bounds__(TPB, 2)
corr_mma(const float* __restrict__ bias, float* __restrict__ out)
{
    extern __shared__ uint4 wfs[];   // 3456 uint4

    const int tid = threadIdx.x;
    for (int i = tid; i < WQ_ELEMS; i += TPB) wfs[i] = WQ_g[i];
    __syncthreads();

    const int lane = tid & 31;
    const int wid  = tid >> 5;
    const int tg = lane >> 2;     // x-group 0..7
    const int tk = lane & 3;      // k-in-group 0..3

    const int gw = blockIdx.x * WPB + wid;  // row id
    if (gw >= 4096) return;                 // tail guard (no barriers below)
    const int vbase = gw << 6;              // full x-row (64 voxels)
    const int z = gw >> 6, y = gw & 63;
    const int x4 = 4 * tg;

    float aA0[16], aA1[16], aB0[16], aB1[16];
#pragma unroll
    for (int i = 0; i < 16; i++) { aA0[i]=0.f; aA1[i]=0.f; aB0[i]=0.f; aB1[i]=0.f; }

    // channel-pair slots: s = kc*2 + j -> c2 = kc*8 + j*4 + tk
    int c2s[4];
#pragma unroll
    for (int s = 0; s < 4; s++) c2s[s] = ((s >> 1) << 3) + ((s & 1) << 2) + tk;

    // in1 fragments: [slot][4] half2 per half
    uint32_t i1A[4][4], i1B[4][4];
#pragma unroll
    for (int s = 0; s < 4; s++) {
        const uint4 tA = *reinterpret_cast<const uint4*>(IN1H + c2s[s] * VOX + vbase + x4);
        const uint4 tB = *reinterpret_cast<const uint4*>(IN1H + c2s[s] * VOX + vbase + 32 + x4);
        i1A[s][0]=tA.x; i1A[s][1]=tA.y; i1A[s][2]=tA.z; i1A[s][3]=tA.w;
        i1B[s][0]=tB.x; i1B[s][1]=tB.y; i1B[s][2]=tB.z; i1B[s][3]=tB.w;
    }

    // pipeline vectors: [j*2 + half] for one kc
    uint4 v01[4], v23[4], vn01[4];
    {   // prologue: kc0 of it=0
        const int zz = z - 1, yy = y - 1;
        const bool ok = ((unsigned)zz < 64u) & ((unsigned)yy < 64u);
        const int rb = (zz << 12) + (yy << 6);
        const uint4 zer = make_uint4(0u,0u,0u,0u);
#pragma unroll
        for (int j = 0; j < 2; j++) {
            v01[j*2]   = ok ? *reinterpret_cast<const uint4*>(IN2H + c2s[j] * VOX + rb + x4)      : zer;
            v01[j*2+1] = ok ? *reinterpret_cast<const uint4*>(IN2H + c2s[j] * VOX + rb + 32 + x4) : zer;
        }
    }

#pragma unroll 1
    for (int it = 0; it < 9; it++) {
        const int zz = z + it / 3 - 1, yy = y + it % 3 - 1;
        const bool ok = ((unsigned)zz < 64u) & ((unsigned)yy < 64u);
        const int rb = (zz << 12) + (yy << 6);
        const uint4 zer = make_uint4(0u,0u,0u,0u);

        // JIT: kc1 vectors of current it
#pragma unroll
        for (int j = 0; j < 2; j++) {
            v23[j*2]   = ok ? *reinterpret_cast<const uint4*>(IN2H + c2s[2+j] * VOX + rb + x4)      : zer;
            v23[j*2+1] = ok ? *reinterpret_cast<const uint4*>(IN2H + c2s[2+j] * VOX + rb + 32 + x4) : zer;
        }
        // prefetch: kc0 vectors of next it
        if (it < 8) {
            const int nit = it + 1;
            const int nzz = z + nit / 3 - 1, nyy = y + nit % 3 - 1;
            const bool nok = ((unsigned)nzz < 64u) & ((unsigned)nyy < 64u);
            const int nrb = (nzz << 12) + (nyy << 6);
#pragma unroll
            for (int j = 0; j < 2; j++) {
                vn01[j*2]   = nok ? *reinterpret_cast<const uint4*>(IN2H + c2s[j] * VOX + nrb + x4)      : zer;
                vn01[j*2+1] = nok ? *reinterpret_cast<const uint4*>(IN2H + c2s[j] * VOX + nrb + 32 + x4) : zer;
            }
        }

#pragma unroll
        for (int kc = 0; kc < 2; kc++) {
            const uint4* vv = kc ? v23 : v01;

            // windows per slot j and half: seam x=31/32 via distance-28 shuffles
            uint32_t wvA0[6], wvB0[6], wvA1[6], wvB1[6];
#pragma unroll
            for (int j = 0; j < 2; j++) {
                const uint4 vA = vv[j*2], vB = vv[j*2+1];
                uint32_t* wA_ = j ? wvA1 : wvA0;
                uint32_t* wB_ = j ? wvB1 : wvB0;
                wA_[1]=vA.x; wA_[2]=vA.y; wA_[3]=vA.z; wA_[4]=vA.w;
                wB_[1]=vB.x; wB_[2]=vB.y; wB_[3]=vB.z; wB_[4]=vB.w;
                const uint32_t upA = __shfl_up_sync(0xffffffffu, vA.w, 4);
                const uint32_t dnA = __shfl_down_sync(0xffffffffu, vA.x, 4);
                const uint32_t upB = __shfl_up_sync(0xffffffffu, vB.w, 4);
                const uint32_t dnB = __shfl_down_sync(0xffffffffu, vB.x, 4);
                const uint32_t seamAB = __shfl_up_sync(0xffffffffu, vB.x, 28);   // tg7 <- tg0: x=32
                const uint32_t seamBA = __shfl_down_sync(0xffffffffu, vA.w, 28); // tg0 <- tg7: x=31
                wA_[0] = (tg == 0) ? 0u : upA;
                wA_[5] = (tg == 7) ? seamAB : dnA;
                wB_[0] = (tg == 0) ? seamBA : upB;
                wB_[5] = (tg == 7) ? 0u : dnB;
            }

#pragma unroll
            for (int dx = 0; dx < 3; dx++) {
                const int chunk = (it * 3 + dx) * 2 + kc;
                const uint4 wA = wfs[chunk * 64 + lane];
                const uint4 wB = wfs[chunk * 64 + 32 + lane];
                half_mma(aA0, aA1, i1A[kc*2], i1A[kc*2+1], wvA0, wvA1, dx, wA, wB);
                half_mma(aB0, aB1, i1B[kc*2], i1B[kc*2+1], wvB0, wvB1, dx, wA, wB);
            }
        }

#pragma unroll
        for (int j = 0; j < 4; j++) v01[j] = vn01[j];
    }

    // epilogue: o = nt*8 + 2tk (+1); x-consecutive -> STG.128 per half
#pragma unroll
    for (int nt = 0; nt < 4; nt++) {
        const int o0 = nt * 8 + 2 * tk;
        const int o1 = o0 + 1;
        if (o0 < NOFF_) {
            const float b = __ldg(bias + o0);
            const float4 rA = make_float4(aA0[nt*4+0]+b, aA0[nt*4+2]+b,
                                          aA1[nt*4+0]+b, aA1[nt*4+2]+b);
            const float4 rB = make_float4(aB0[nt*4+0]+b, aB0[nt*4+2]+b,
                                          aB1[nt*4+0]+b, aB1[nt*4+2]+b);
            *reinterpret_cast<float4*>(out + o0 * VOX + vbase + x4)      = rA;
            *reinterpret_cast<float4*>(out + o0 * VOX + vbase + 32 + x4) = rB;
        }
        if (o1 < NOFF_) {
            const float b = __ldg(bias + o1);
            const float4 rA = make_float4(aA0[nt*4+1]+b, aA0[nt*4+3]+b,
                                          aA1[nt*4+1]+b, aA1[nt*4+3]+b);
            const float4 rB = make_float4(aB0[nt*4+1]+b, aB0[nt*4+3]+b,
                                          aB1[nt*4+1]+b, aB1[nt*4+3]+b);
            *reinterpret_cast<float4*>(out + o1 * VOX + vbase + x4)      = rA;
            *reinterpret_cast<float4*>(out + o1 * VOX + vbase + 32 + x4) = rB;
        }
    }
}

extern "C" void kernel_launch(void* const* d_in, const int* in_sizes, int n_in,
                              void* d_out, int out_size) {
    const float* in1 = (const float*)d_in[0];
    const float* in2 = (const float*)d_in[1];
    const float* w   = (const float*)d_in[2];
    const float* b   = (const float*)d_in[3];
    float* out = (float*)d_out;

    convert_inputs<<<(2 * PAIRS * VOX / 4 + 255) / 256, 256>>>(in1, in2);
    stage_weights<<<(WQ_ELEMS + 255) / 256, 256>>>(w);

    const int smem = WQ_ELEMS * (int)sizeof(uint4);   // 55296
    cudaFuncSetAttribute(corr_mma,
                         cudaFuncAttributeMaxDynamicSharedMemorySize, smem);
    corr_mma<<<(4096 + WPB - 1) / WPB, TPB, smem>>>(b, out);
}

// round 12
// speedup vs baseline: 1.0551x; 1.0551x over previous
#include <cuda_runtime.h>
#include <cuda_fp16.h>
#include <cstdint>

// CorrTorch via warp-level fp16 mma.sync (m16n8k16), x-consecutive lanes.
// R12 = R10 core (M=32/warp, kc-merged depth-2 pipeline) with:
//  - prepass converts ONLY in2 to fp16 pair-interleaved (in1 is read once ->
//    converted inline in the main kernel; saves 48MB of prepass traffic)
//  - weight staging merged into the prepass launch
//  - warp-uniform skip of OOB (dz,dy) iterations

#define C_    32
#define NOFF_ 27
#define VOX   262144                  // 64^3
#define PAIRS 16                      // channel pairs
#define NCHUNK 54                     // 27 offsets * 2 k16-chunks
#define WQ_ELEMS (NCHUNK * 64)        // uint4 count = 3456 (55296 B)
#define TPB   256
#define CONV_BLOCKS 4096              // PAIRS*VOX/4/256

__device__ uint4 WQ_g[WQ_ELEMS];            // packed fp16 weight fragments
__device__ uint32_t IN2H[PAIRS * VOX];      // half2 {ch_even,ch_odd} (16 MB)

__device__ __forceinline__ uint32_t f2h2(float lo, float hi) {
    uint32_t r;
    asm("cvt.rn.f16x2.f32 %0, %1, %2;" : "=r"(r) : "f"(hi), "f"(lo));
    return r;
}
__device__ __forceinline__ uint32_t hmul2(uint32_t a, uint32_t b) {
    uint32_t d;
    asm("mul.rn.f16x2 %0, %1, %2;" : "=r"(d) : "r"(a), "r"(b));
    return d;
}

// ---------------- prepass: convert in2 + stage weights (one launch) --------
__global__ void prep(const float* __restrict__ in2, const float* __restrict__ w) {
    if (blockIdx.x < CONV_BLOCKS) {
        const int idx = blockIdx.x * 256 + threadIdx.x;   // < PAIRS*VOX/4
        const int c2 = idx / (VOX / 4);
        const int v4 = (idx - c2 * (VOX / 4)) * 4;
        const float4 a = __ldg(reinterpret_cast<const float4*>(in2 + (2 * c2) * VOX + v4));
        const float4 b = __ldg(reinterpret_cast<const float4*>(in2 + (2 * c2 + 1) * VOX + v4));
        uint4 o;
        o.x = f2h2(a.x, b.x); o.y = f2h2(a.y, b.y);
        o.z = f2h2(a.z, b.z); o.w = f2h2(a.w, b.w);
        *reinterpret_cast<uint4*>(IN2H + c2 * VOX + v4) = o;
    } else {
        const int idx = (blockIdx.x - CONV_BLOCKS) * 256 + threadIdx.x;
        if (idx >= WQ_ELEMS) return;
        const int chunk = idx >> 6;            // off*2 + kc
        const int rem = idx & 63;
        const int h = rem >> 5;
        const int lane = rem & 31;
        const int off = chunk >> 1, kc = chunk & 1;
        const int tg = lane >> 2, tk = lane & 3;
        const int k0 = off * 32 + kc * 16;
        const float s = 0.17677669529663688f;   // 1/sqrt(32)
        const int oa = (2 * h) * 8 + tg;
        const int ob = (2 * h + 1) * 8 + tg;
        uint4 r;
        r.x = f2h2(w[oa * 864 + k0 + 2 * tk] * s,     w[oa * 864 + k0 + 2 * tk + 1] * s);
        r.y = f2h2(w[oa * 864 + k0 + 2 * tk + 8] * s, w[oa * 864 + k0 + 2 * tk + 9] * s);
        r.z = (ob < NOFF_) ? f2h2(w[ob * 864 + k0 + 2 * tk] * s,
                                  w[ob * 864 + k0 + 2 * tk + 1] * s) : 0u;
        r.w = (ob < NOFF_) ? f2h2(w[ob * 864 + k0 + 2 * tk + 8] * s,
                                  w[ob * 864 + k0 + 2 * tk + 9] * s) : 0u;
        WQ_g[idx] = r;
    }
}

// ---------------- mma helper ----------------
__device__ __forceinline__ void mma16816(float* d, uint32_t a0, uint32_t a1,
                                         uint32_t a2, uint32_t a3,
                                         uint32_t b0, uint32_t b1) {
    asm volatile(
        "mma.sync.aligned.m16n8k16.row.col.f32.f16.f16.f32 "
        "{%0,%1,%2,%3}, {%4,%5,%6,%7}, {%8,%9}, {%0,%1,%2,%3};"
        : "+f"(d[0]), "+f"(d[1]), "+f"(d[2]), "+f"(d[3])
        : "r"(a0), "r"(a1), "r"(a2), "r"(a3), "r"(b0), "r"(b1));
}

// ---------------- main kernel ----------------
__global__ void __launch_bounds__(TPB, 2)
corr_mma(const float* __restrict__ in1,
         const float* __restrict__ bias, float* __restrict__ out)
{
    extern __shared__ uint4 wfs[];   // 3456 uint4

    const int tid = threadIdx.x;
    for (int i = tid; i < WQ_ELEMS; i += TPB) wfs[i] = WQ_g[i];
    __syncthreads();

    const int lane = tid & 31;
    const int wid  = tid >> 5;
    const int tg = lane >> 2;     // x-group 0..7
    const int tk = lane & 3;      // k-in-group 0..3

    const int gw = blockIdx.x * 8 + wid;    // 0..8191
    const int vbase = gw * 32;              // 32 consecutive-x voxels
    const int xw0 = vbase & 63;             // 0 or 32
    const int z = vbase >> 12, y = (vbase >> 6) & 63;
    const int gx = xw0 + 4 * tg;            // lane's first x
    const bool lo_real = (xw0 == 32);       // lo halo from memory; else hi
    const int  ex = lo_real ? 31 : 32;      // the one real edge x

    float acc0[16], acc1[16];
#pragma unroll
    for (int i = 0; i < 16; i++) { acc0[i] = 0.f; acc1[i] = 0.f; }

    // channel-pair slots: s = kc*2 + half -> c2 = (s>>1)*8 + (s&1)*4 + tk
    int c2s[4];
#pragma unroll
    for (int s = 0; s < 4; s++) c2s[s] = ((s >> 1) << 3) + ((s & 1) << 2) + tk;

    // in1 fragments converted inline from fp32: i1v[s][j] = h2(in1[2c2][x], in1[2c2+1][x])
    uint32_t i1v[4][4];
#pragma unroll
    for (int s = 0; s < 4; s++) {
        const float* p0 = in1 + (2 * c2s[s]) * VOX + vbase + 4 * tg;
        const float4 a = __ldg(reinterpret_cast<const float4*>(p0));
        const float4 b = __ldg(reinterpret_cast<const float4*>(p0 + VOX));
        i1v[s][0] = f2h2(a.x, b.x); i1v[s][1] = f2h2(a.y, b.y);
        i1v[s][2] = f2h2(a.z, b.z); i1v[s][3] = f2h2(a.w, b.w);
    }

    // ---- depth-2 pipeline over 9 (dz,dy) iterations, both kc together ----
    uint4 v[4], vn[4]; uint32_t e[4], en[4];
    bool okc;
    {
        const int zz = z - 1, yy = y - 1;
        okc = ((unsigned)zz < 64u) & ((unsigned)yy < 64u);
        const int rb = (zz << 12) + (yy << 6);
        const uint4 zer = make_uint4(0u, 0u, 0u, 0u);
#pragma unroll
        for (int s = 0; s < 4; s++) {
            v[s] = okc ? *reinterpret_cast<const uint4*>(IN2H + c2s[s] * VOX + rb + gx) : zer;
            e[s] = okc ? IN2H[c2s[s] * VOX + rb + ex] : 0u;
        }
    }

#pragma unroll 1
    for (int it = 0; it < 9; it++) {
        bool okn = false;
        if (it < 8) {
            const int nit = it + 1;
            const int zz = z + nit / 3 - 1, yy = y + nit % 3 - 1;
            okn = ((unsigned)zz < 64u) & ((unsigned)yy < 64u);
            const int rb = (zz << 12) + (yy << 6);
            const uint4 zer = make_uint4(0u, 0u, 0u, 0u);
#pragma unroll
            for (int s = 0; s < 4; s++) {
                vn[s] = okn ? *reinterpret_cast<const uint4*>(IN2H + c2s[s] * VOX + rb + gx) : zer;
                en[s] = okn ? IN2H[c2s[s] * VOX + rb + ex] : 0u;
            }
        }

        if (okc) {   // warp-uniform: OOB rows contribute exactly zero
#pragma unroll
            for (int kc = 0; kc < 2; kc++) {
                // 6-wide half2 windows for this kc's two slots
                uint32_t wv0[6], wv1[6];
#pragma unroll
                for (int h = 0; h < 2; h++) {
                    const uint4 vv = v[kc * 2 + h];
                    const uint32_t ee = e[kc * 2 + h];
                    uint32_t* wv = h ? wv1 : wv0;
                    wv[1] = vv.x; wv[2] = vv.y; wv[3] = vv.z; wv[4] = vv.w;
                    const uint32_t up = __shfl_up_sync(0xffffffffu, vv.w, 4);
                    const uint32_t dn = __shfl_down_sync(0xffffffffu, vv.x, 4);
                    wv[0] = (tg == 0) ? (lo_real ? ee : 0u) : up;
                    wv[5] = (tg == 7) ? (lo_real ? 0u : ee) : dn;
                }

#pragma unroll
                for (int dx = 0; dx < 3; dx++) {
                    const int chunk = (it * 3 + dx) * 2 + kc;
                    const uint4 wA = wfs[chunk * 64 + lane];
                    const uint4 wB = wfs[chunk * 64 + 32 + lane];

#pragma unroll
                    for (int mt = 0; mt < 2; mt++) {
                        const int p0 = 2 * mt, p1 = 2 * mt + 1;
                        const uint32_t a0 = hmul2(i1v[kc * 2][p0],     wv0[dx + p0]);
                        const uint32_t a1 = hmul2(i1v[kc * 2][p1],     wv0[dx + p1]);
                        const uint32_t a2 = hmul2(i1v[kc * 2 + 1][p0], wv1[dx + p0]);
                        const uint32_t a3 = hmul2(i1v[kc * 2 + 1][p1], wv1[dx + p1]);
                        float* acc = mt ? acc1 : acc0;
                        mma16816(acc + 0,  a0, a1, a2, a3, wA.x, wA.y);
                        mma16816(acc + 4,  a0, a1, a2, a3, wA.z, wA.w);
                        mma16816(acc + 8,  a0, a1, a2, a3, wB.x, wB.y);
                        mma16816(acc + 12, a0, a1, a2, a3, wB.z, wB.w);
                    }
                }
            }
        }

        okc = okn;
#pragma unroll
        for (int s = 0; s < 4; s++) { v[s] = vn[s]; e[s] = en[s]; }
    }

    // epilogue: o = nt*8 + 2tk (+1); x = 4tg..4tg+3 -> one STG.128 per o
#pragma unroll
    for (int nt = 0; nt < 4; nt++) {
        const int o0 = nt * 8 + 2 * tk;
        const int o1 = o0 + 1;
        if (o0 < NOFF_) {
            const float b = __ldg(bias + o0);
            const float4 r = make_float4(acc0[nt * 4 + 0] + b, acc0[nt * 4 + 2] + b,
                                         acc1[nt * 4 + 0] + b, acc1[nt * 4 + 2] + b);
            *reinterpret_cast<float4*>(out + o0 * VOX + vbase + 4 * tg) = r;
        }
        if (o1 < NOFF_) {
            const float b = __ldg(bias + o1);
            const float4 r = make_float4(acc0[nt * 4 + 1] + b, acc0[nt * 4 + 3] + b,
                                         acc1[nt * 4 + 1] + b, acc1[nt * 4 + 3] + b);
            *reinterpret_cast<float4*>(out + o1 * VOX + vbase + 4 * tg) = r;
        }
    }
}

extern "C" void kernel_launch(void* const* d_in, const int* in_sizes, int n_in,
                              void* d_out, int out_size) {
    const float* in1 = (const float*)d_in[0];
    const float* in2 = (const float*)d_in[1];
    const float* w   = (const float*)d_in[2];
    const float* b   = (const float*)d_in[3];
    float* out = (float*)d_out;

    prep<<<CONV_BLOCKS + (WQ_ELEMS + 255) / 256, 256>>>(in2, w);

    const int smem = WQ_ELEMS * (int)sizeof(uint4);   // 55296
    cudaFuncSetAttribute(corr_mma,
                         cudaFuncAttributeMaxDynamicSharedMemorySize, smem);
    corr_mma<<<1024, TPB, smem>>>(in1, b, out);
}

// round 13
// speedup vs baseline: 1.1394x; 1.0799x over previous
#include <cuda_runtime.h>
#include <cuda_fp16.h>
#include <cstdint>

// CorrTorch via warp-level fp16 mma.sync (m16n8k16), x-consecutive lanes.
// R13 = R10 main loop (unconditional body; predicated loads handle OOB) +
// R12's lean prepass (convert ONLY in2 to fp16 pair-interleaved, stage
// weights in the same launch, convert in1 inline in the main prologue).

#define C_    32
#define NOFF_ 27
#define VOX   262144                  // 64^3
#define PAIRS 16                      // channel pairs
#define NCHUNK 54                     // 27 offsets * 2 k16-chunks
#define WQ_ELEMS (NCHUNK * 64)        // uint4 count = 3456 (55296 B)
#define TPB   256
#define CONV_BLOCKS 4096              // PAIRS*VOX/4/256

__device__ uint4 WQ_g[WQ_ELEMS];            // packed fp16 weight fragments
__device__ uint32_t IN2H[PAIRS * VOX];      // half2 {ch_even,ch_odd} (16 MB)

__device__ __forceinline__ uint32_t f2h2(float lo, float hi) {
    uint32_t r;
    asm("cvt.rn.f16x2.f32 %0, %1, %2;" : "=r"(r) : "f"(hi), "f"(lo));
    return r;
}
__device__ __forceinline__ uint32_t hmul2(uint32_t a, uint32_t b) {
    uint32_t d;
    asm("mul.rn.f16x2 %0, %1, %2;" : "=r"(d) : "r"(a), "r"(b));
    return d;
}

// ---------------- prepass: convert in2 + stage weights (one launch) --------
__global__ void prep(const float* __restrict__ in2, const float* __restrict__ w) {
    if (blockIdx.x < CONV_BLOCKS) {
        const int idx = blockIdx.x * 256 + threadIdx.x;   // < PAIRS*VOX/4
        const int c2 = idx / (VOX / 4);
        const int v4 = (idx - c2 * (VOX / 4)) * 4;
        const float4 a = __ldg(reinterpret_cast<const float4*>(in2 + (2 * c2) * VOX + v4));
        const float4 b = __ldg(reinterpret_cast<const float4*>(in2 + (2 * c2 + 1) * VOX + v4));
        uint4 o;
        o.x = f2h2(a.x, b.x); o.y = f2h2(a.y, b.y);
        o.z = f2h2(a.z, b.z); o.w = f2h2(a.w, b.w);
        *reinterpret_cast<uint4*>(IN2H + c2 * VOX + v4) = o;
    } else {
        const int idx = (blockIdx.x - CONV_BLOCKS) * 256 + threadIdx.x;
        if (idx >= WQ_ELEMS) return;
        const int chunk = idx >> 6;            // off*2 + kc
        const int rem = idx & 63;
        const int h = rem >> 5;
        const int lane = rem & 31;
        const int off = chunk >> 1, kc = chunk & 1;
        const int tg = lane >> 2, tk = lane & 3;
        const int k0 = off * 32 + kc * 16;
        const float s = 0.17677669529663688f;   // 1/sqrt(32)
        const int oa = (2 * h) * 8 + tg;
        const int ob = (2 * h + 1) * 8 + tg;
        uint4 r;
        r.x = f2h2(w[oa * 864 + k0 + 2 * tk] * s,     w[oa * 864 + k0 + 2 * tk + 1] * s);
        r.y = f2h2(w[oa * 864 + k0 + 2 * tk + 8] * s, w[oa * 864 + k0 + 2 * tk + 9] * s);
        r.z = (ob < NOFF_) ? f2h2(w[ob * 864 + k0 + 2 * tk] * s,
                                  w[ob * 864 + k0 + 2 * tk + 1] * s) : 0u;
        r.w = (ob < NOFF_) ? f2h2(w[ob * 864 + k0 + 2 * tk + 8] * s,
                                  w[ob * 864 + k0 + 2 * tk + 9] * s) : 0u;
        WQ_g[idx] = r;
    }
}

// ---------------- mma helper ----------------
__device__ __forceinline__ void mma16816(float* d, uint32_t a0, uint32_t a1,
                                         uint32_t a2, uint32_t a3,
                                         uint32_t b0, uint32_t b1) {
    asm volatile(
        "mma.sync.aligned.m16n8k16.row.col.f32.f16.f16.f32 "
        "{%0,%1,%2,%3}, {%4,%5,%6,%7}, {%8,%9}, {%0,%1,%2,%3};"
        : "+f"(d[0]), "+f"(d[1]), "+f"(d[2]), "+f"(d[3])
        : "r"(a0), "r"(a1), "r"(a2), "r"(a3), "r"(b0), "r"(b1));
}

// ---------------- main kernel ----------------
__global__ void __launch_bounds__(TPB, 2)
corr_mma(const float* __restrict__ in1,
         const float* __restrict__ bias, float* __restrict__ out)
{
    extern __shared__ uint4 wfs[];   // 3456 uint4

    const int tid = threadIdx.x;
    for (int i = tid; i < WQ_ELEMS; i += TPB) wfs[i] = WQ_g[i];
    __syncthreads();

    const int lane = tid & 31;
    const int wid  = tid >> 5;
    const int tg = lane >> 2;     // x-group 0..7
    const int tk = lane & 3;      // k-in-group 0..3

    const int gw = blockIdx.x * 8 + wid;    // 0..8191
    const int vbase = gw * 32;              // 32 consecutive-x voxels
    const int xw0 = vbase & 63;             // 0 or 32
    const int z = vbase >> 12, y = (vbase >> 6) & 63;
    const int gx = xw0 + 4 * tg;            // lane's first x
    const bool lo_real = (xw0 == 32);       // lo halo from memory; else hi
    const int  ex = lo_real ? 31 : 32;      // the one real edge x

    float acc0[16], acc1[16];
#pragma unroll
    for (int i = 0; i < 16; i++) { acc0[i] = 0.f; acc1[i] = 0.f; }

    // channel-pair slots: s = kc*2 + half -> c2 = (s>>1)*8 + (s&1)*4 + tk
    int c2s[4];
#pragma unroll
    for (int s = 0; s < 4; s++) c2s[s] = ((s >> 1) << 3) + ((s & 1) << 2) + tk;

    // in1 fragments converted inline from fp32
    uint32_t i1v[4][4];
#pragma unroll
    for (int s = 0; s < 4; s++) {
        const float* p0 = in1 + (2 * c2s[s]) * VOX + vbase + 4 * tg;
        const float4 a = __ldg(reinterpret_cast<const float4*>(p0));
        const float4 b = __ldg(reinterpret_cast<const float4*>(p0 + VOX));
        i1v[s][0] = f2h2(a.x, b.x); i1v[s][1] = f2h2(a.y, b.y);
        i1v[s][2] = f2h2(a.z, b.z); i1v[s][3] = f2h2(a.w, b.w);
    }

    // ---- depth-2 pipeline over 9 (dz,dy) iterations, both kc together ----
    uint4 v[4], vn[4]; uint32_t e[4], en[4];
    {
        const int zz = z - 1, yy = y - 1;
        const bool ok = ((unsigned)zz < 64u) & ((unsigned)yy < 64u);
        const int rb = (zz << 12) + (yy << 6);
        const uint4 zer = make_uint4(0u, 0u, 0u, 0u);
#pragma unroll
        for (int s = 0; s < 4; s++) {
            v[s] = ok ? *reinterpret_cast<const uint4*>(IN2H + c2s[s] * VOX + rb + gx) : zer;
            e[s] = ok ? IN2H[c2s[s] * VOX + rb + ex] : 0u;
        }
    }

#pragma unroll 1
    for (int it = 0; it < 9; it++) {
        if (it < 8) {
            const int nit = it + 1;
            const int zz = z + nit / 3 - 1, yy = y + nit % 3 - 1;
            const bool ok = ((unsigned)zz < 64u) & ((unsigned)yy < 64u);
            const int rb = (zz << 12) + (yy << 6);
            const uint4 zer = make_uint4(0u, 0u, 0u, 0u);
#pragma unroll
            for (int s = 0; s < 4; s++) {
                vn[s] = ok ? *reinterpret_cast<const uint4*>(IN2H + c2s[s] * VOX + rb + gx) : zer;
                en[s] = ok ? IN2H[c2s[s] * VOX + rb + ex] : 0u;
            }
        }

#pragma unroll
        for (int kc = 0; kc < 2; kc++) {
            // 6-wide half2 windows for this kc's two slots
            uint32_t wv0[6], wv1[6];
#pragma unroll
            for (int h = 0; h < 2; h++) {
                const uint4 vv = v[kc * 2 + h];
                const uint32_t ee = e[kc * 2 + h];
                uint32_t* wv = h ? wv1 : wv0;
                wv[1] = vv.x; wv[2] = vv.y; wv[3] = vv.z; wv[4] = vv.w;
                const uint32_t up = __shfl_up_sync(0xffffffffu, vv.w, 4);
                const uint32_t dn = __shfl_down_sync(0xffffffffu, vv.x, 4);
                wv[0] = (tg == 0) ? (lo_real ? ee : 0u) : up;
                wv[5] = (tg == 7) ? (lo_real ? 0u : ee) : dn;
            }

#pragma unroll
            for (int dx = 0; dx < 3; dx++) {
                const int chunk = (it * 3 + dx) * 2 + kc;
                const uint4 wA = wfs[chunk * 64 + lane];
                const uint4 wB = wfs[chunk * 64 + 32 + lane];

#pragma unroll
                for (int mt = 0; mt < 2; mt++) {
                    const int p0 = 2 * mt, p1 = 2 * mt + 1;
                    const uint32_t a0 = hmul2(i1v[kc * 2][p0],     wv0[dx + p0]);
                    const uint32_t a1 = hmul2(i1v[kc * 2][p1],     wv0[dx + p1]);
                    const uint32_t a2 = hmul2(i1v[kc * 2 + 1][p0], wv1[dx + p0]);
                    const uint32_t a3 = hmul2(i1v[kc * 2 + 1][p1], wv1[dx + p1]);
                    float* acc = mt ? acc1 : acc0;
                    mma16816(acc + 0,  a0, a1, a2, a3, wA.x, wA.y);
                    mma16816(acc + 4,  a0, a1, a2, a3, wA.z, wA.w);
                    mma16816(acc + 8,  a0, a1, a2, a3, wB.x, wB.y);
                    mma16816(acc + 12, a0, a1, a2, a3, wB.z, wB.w);
                }
            }
        }

#pragma unroll
        for (int s = 0; s < 4; s++) { v[s] = vn[s]; e[s] = en[s]; }
    }

    // epilogue: o = nt*8 + 2tk (+1); x = 4tg..4tg+3 -> one STG.128 per o
#pragma unroll
    for (int nt = 0; nt < 4; nt++) {
        const int o0 = nt * 8 + 2 * tk;
        const int o1 = o0 + 1;
        if (o0 < NOFF_) {
            const float b = __ldg(bias + o0);
            const float4 r = make_float4(acc0[nt * 4 + 0] + b, acc0[nt * 4 + 2] + b,
                                         acc1[nt * 4 + 0] + b, acc1[nt * 4 + 2] + b);
            *reinterpret_cast<float4*>(out + o0 * VOX + vbase + 4 * tg) = r;
        }
        if (o1 < NOFF_) {
            const float b = __ldg(bias + o1);
            const float4 r = make_float4(acc0[nt * 4 + 1] + b, acc0[nt * 4 + 3] + b,
                                         acc1[nt * 4 + 1] + b, acc1[nt * 4 + 3] + b);
            *reinterpret_cast<float4*>(out + o1 * VOX + vbase + 4 * tg) = r;
        }
    }
}

extern "C" void kernel_launch(void* const* d_in, const int* in_sizes, int n_in,
                              void* d_out, int out_size) {
    const float* in1 = (const float*)d_in[0];
    const float* in2 = (const float*)d_in[1];
    const float* w   = (const float*)d_in[2];
    const float* b   = (const float*)d_in[3];
    float* out = (float*)d_out;

    prep<<<CONV_BLOCKS + (WQ_ELEMS + 255) / 256, 256>>>(in2, w);

    const int smem = WQ_ELEMS * (int)sizeof(uint4);   // 55296
    cudaFuncSetAttribute(corr_mma,
                         cudaFuncAttributeMaxDynamicSharedMemorySize, smem);
    corr_mma<<<1024, TPB, smem>>>(in1, b, out);
}